// round 4
// baseline (speedup 1.0000x reference)
#include <cuda_runtime.h>
#include <cstdint>

// Problem constants (fixed shapes for this dataset)
constexpr int NN = 100000;   // nodes
constexpr int EE = 1600000;  // edges (without self loops)
constexpr int SCAN_NBLK = (NN + 1023) / 1024;  // 98

// ---------------- static device scratch (no allocation allowed) --------------
__device__ int   g_is64;             // 1 if edge_index is int64, 0 if int32
__device__ int   g_cnt[NN];          // in-degree counts, later reused as cursor
__device__ int   g_rowptr[NN + 1];   // CSR row pointers (by dst)
__device__ int   g_bsum[128];        // scan block sums
__device__ float g_dinv[NN];         // deg^-1/2
__device__ int   g_col[EE];          // CSR: src node per edge
__device__ float g_ew[EE];           // CSR: edge norm = dinv[src]*dinv[dst]
__device__ float g_buf1[(size_t)NN * 128];
__device__ float g_buf2[(size_t)NN * 128];

// Resolve buffer selector in DEVICE code.
__device__ __forceinline__ const float* sel_src(const float* ext, int s) {
    return s == 0 ? ext : (s == 1 ? (const float*)g_buf1 : (const float*)g_buf2);
}
__device__ __forceinline__ float* sel_dst(float* ext, int s) {
    return s == 0 ? ext : (s == 1 ? (float*)g_buf1 : (float*)g_buf2);
}

// ---------------- dtype detection --------------------------------------------
// int64 entries (values in [0, 1e5), nonneg) have zero high words at odd 32-bit
// positions. int32 data has random indices there (all-zero prob ~0).
__global__ void k_detect(const int* __restrict__ w) {
    int lane = threadIdx.x;  // 32 threads
    int acc = 0;
    for (int i = lane; i < 1024; i += 32) acc |= w[2 * i + 1];
#pragma unroll
    for (int off = 16; off > 0; off >>= 1)
        acc |= __shfl_xor_sync(0xffffffffu, acc, off);
    if (lane == 0) g_is64 = (acc == 0) ? 1 : 0;
}

__device__ __forceinline__ int load_idx(const int* __restrict__ w, int pos, int is64) {
    return is64 ? w[2 * pos] : w[pos];  // little-endian low word == value (<2^31)
}

// ---------------- preprocessing kernels --------------------------------------
__global__ void k_zero_cnt() {
    int i = blockIdx.x * blockDim.x + threadIdx.x;
    if (i < NN) g_cnt[i] = 0;
}

__global__ void k_count(const int* __restrict__ w, int E) {
    int e = blockIdx.x * blockDim.x + threadIdx.x;
    if (e < E) {
        int is64 = g_is64;
        int d = load_idx(w, E + e, is64);  // dst row
        if ((unsigned)d < (unsigned)NN) atomicAdd(&g_cnt[d], 1);
    }
}

__global__ void k_dinv() {
    int i = blockIdx.x * blockDim.x + threadIdx.x;
    if (i < NN) {
        // +1 for self loop; deg >= 1 always
        g_dinv[i] = rsqrtf((float)(g_cnt[i] + 1));
    }
}

// scan pass 1: per-block (1024 elems) total -> g_bsum
__global__ void k_scan1() {
    __shared__ int s[256];
    int b = blockIdx.x, tid = threadIdx.x;
    int base = b * 1024 + tid * 4;
    int local = 0;
#pragma unroll
    for (int j = 0; j < 4; j++) {
        int i = base + j;
        if (i < NN) local += g_cnt[i];
    }
    s[tid] = local;
    __syncthreads();
    for (int off = 128; off > 0; off >>= 1) {
        if (tid < off) s[tid] += s[tid + off];
        __syncthreads();
    }
    if (tid == 0) g_bsum[b] = s[0];
}

// scan pass 2: exclusive scan of block sums (single block)
__global__ void k_scan2() {
    __shared__ int s[128];
    int tid = threadIdx.x;
    int v = (tid < SCAN_NBLK) ? g_bsum[tid] : 0;
    s[tid] = v;
    __syncthreads();
    for (int off = 1; off < 128; off <<= 1) {
        int t = (tid >= off) ? s[tid - off] : 0;
        __syncthreads();
        s[tid] += t;
        __syncthreads();
    }
    if (tid < SCAN_NBLK) g_bsum[tid] = s[tid] - v;  // exclusive
    if (tid == 127) g_rowptr[NN] = s[127];          // total <= E
}

// scan pass 3: write rowptr
__global__ void k_scan3() {
    __shared__ int s[256];
    int b = blockIdx.x, tid = threadIdx.x;
    int base = b * 1024 + tid * 4;
    int v[4];
#pragma unroll
    for (int j = 0; j < 4; j++) {
        int i = base + j;
        v[j] = (i < NN) ? g_cnt[i] : 0;
    }
    int local = v[0] + v[1] + v[2] + v[3];
    s[tid] = local;
    __syncthreads();
    for (int off = 1; off < 256; off <<= 1) {
        int t = (tid >= off) ? s[tid - off] : 0;
        __syncthreads();
        s[tid] += t;
        __syncthreads();
    }
    int excl = s[tid] - local + g_bsum[b];
#pragma unroll
    for (int j = 0; j < 4; j++) {
        int i = base + j;
        if (i < NN) g_rowptr[i] = excl;
        excl += v[j];
    }
}

__global__ void k_cursor() {
    int i = blockIdx.x * blockDim.x + threadIdx.x;
    if (i < NN) g_cnt[i] = g_rowptr[i];
}

__global__ void k_scatter(const int* __restrict__ w, int E) {
    int e = blockIdx.x * blockDim.x + threadIdx.x;
    if (e < E) {
        int is64 = g_is64;
        int s = load_idx(w, e, is64);
        int d = load_idx(w, E + e, is64);
        if ((unsigned)s < (unsigned)NN && (unsigned)d < (unsigned)NN) {
            int pos = atomicAdd(&g_cnt[d], 1);
            g_col[pos] = s;
            g_ew[pos]  = g_dinv[s] * g_dinv[d];
        }
    }
}

// ---------------- aggregation: warp per node, CSR by dst ---------------------
// out[i] = dinv[i]^2 * h[i] + sum_e w_e * h[col_e]   (+bias, relu optional)
template <int CH, bool BIAS, bool RELU>
__global__ void k_agg(const float* __restrict__ hext, int hs,
                      float* __restrict__ oext, int ds,
                      const float* __restrict__ bias) {
    const float* __restrict__ h = sel_src(hext, hs);
    float* __restrict__ out = sel_dst(oext, ds);
    int warp = (blockIdx.x * blockDim.x + threadIdx.x) >> 5;
    int lane = threadIdx.x & 31;
    if (warp >= NN) return;
    constexpr int K = (CH + 31) / 32;
    float acc[K];
    float sd = g_dinv[warp];
    sd *= sd;
#pragma unroll
    for (int k = 0; k < K; k++) {
        int c = k * 32 + lane;
        acc[k] = (c < CH) ? sd * h[(size_t)warp * CH + c] : 0.f;
    }
    int beg = g_rowptr[warp], end = g_rowptr[warp + 1];
    for (int e = beg; e < end; e++) {
        int s = g_col[e];
        float wgt = g_ew[e];
        const float* hr = h + (size_t)s * CH;
#pragma unroll
        for (int k = 0; k < K; k++) {
            int c = k * 32 + lane;
            if (c < CH) acc[k] += wgt * __ldg(&hr[c]);
        }
    }
#pragma unroll
    for (int k = 0; k < K; k++) {
        int c = k * 32 + lane;
        if (c < CH) {
            float v = acc[k];
            if (BIAS) v += bias[c];
            if (RELU) v = fmaxf(v, 0.f);
            out[(size_t)warp * CH + c] = v;
        }
    }
}

// ---------------- dense GEMM: out = h @ W (+b, relu) -------------------------
// K-chunked so everything fits in STATIC shared (<48KB, no attribute calls).
// Block: BN=32 nodes, full OUT width. blockDim = (OUT/4, 8); 4x4 per thread.
template <int IN, int OUT, int KC, bool BIAS, bool RELU>
__global__ void k_gemm(const float* __restrict__ hext, int hs,
                       const float* __restrict__ W,
                       const float* __restrict__ b,
                       float* __restrict__ oext, int ds) {
    const float* __restrict__ h = sel_src(hext, hs);
    float* __restrict__ out = sel_dst(oext, ds);
    constexpr int BN = 32;
    constexpr int HS = BN + 4;  // float4-aligned, bank-spread
    __shared__ float Wsm[KC * OUT];
    __shared__ float Hsm[KC * HS];

    int tid = threadIdx.y * blockDim.x + threadIdx.x;
    int nthreads = blockDim.x * blockDim.y;
    int n0blk = blockIdx.x * BN;

    int c0 = threadIdx.x * 4;
    int n0 = threadIdx.y * 4;
    float acc[4][4];
#pragma unroll
    for (int a = 0; a < 4; a++)
#pragma unroll
        for (int c = 0; c < 4; c++) acc[a][c] = 0.f;

    for (int kc0 = 0; kc0 < IN; kc0 += KC) {
        // stage W chunk (rows kc0..kc0+KC-1 are contiguous in row-major W)
        for (int i = tid; i < KC * OUT; i += nthreads) Wsm[i] = W[kc0 * OUT + i];
        // stage H tile transposed: Hsm[k][n]
        for (int i = tid; i < BN * KC; i += nthreads) {
            int n = i / KC, k = i % KC;
            int node = n0blk + n;
            Hsm[k * HS + n] = (node < NN) ? h[(size_t)node * IN + kc0 + k] : 0.f;
        }
        __syncthreads();

#pragma unroll 4
        for (int k = 0; k < KC; k++) {
            float4 hv4 = *(const float4*)&Hsm[k * HS + n0];
            float4 wv4 = *(const float4*)&Wsm[k * OUT + c0];
            float hv[4] = {hv4.x, hv4.y, hv4.z, hv4.w};
            float wv[4] = {wv4.x, wv4.y, wv4.z, wv4.w};
#pragma unroll
            for (int a = 0; a < 4; a++)
#pragma unroll
                for (int c = 0; c < 4; c++) acc[a][c] += hv[a] * wv[c];
        }
        __syncthreads();
    }

    float bv[4] = {0.f, 0.f, 0.f, 0.f};
    if (BIAS) {
        float4 b4 = *(const float4*)&b[c0];
        bv[0] = b4.x; bv[1] = b4.y; bv[2] = b4.z; bv[3] = b4.w;
    }
#pragma unroll
    for (int a = 0; a < 4; a++) {
        int node = n0blk + n0 + a;
        if (node < NN) {
            float t0 = acc[a][0] + bv[0];
            float t1 = acc[a][1] + bv[1];
            float t2 = acc[a][2] + bv[2];
            float t3 = acc[a][3] + bv[3];
            if (RELU) {
                t0 = fmaxf(t0, 0.f); t1 = fmaxf(t1, 0.f);
                t2 = fmaxf(t2, 0.f); t3 = fmaxf(t3, 0.f);
            }
            float4 o; o.x = t0; o.y = t1; o.z = t2; o.w = t3;
            *(float4*)&out[(size_t)node * OUT + c0] = o;
        }
    }
}

// ---------------- launch ------------------------------------------------------
extern "C" void kernel_launch(void* const* d_in, const int* in_sizes, int n_in,
                              void* d_out, int out_size) {
    const float* x  = (const float*)d_in[0];
    const int* ei32 = (const int*)d_in[1];   // edge_index words (int32 or int64)
    const float* W1 = (const float*)d_in[2];
    const float* b1 = (const float*)d_in[3];
    const float* W2 = (const float*)d_in[4];
    const float* b2 = (const float*)d_in[5];
    const float* W3 = (const float*)d_in[6];
    const float* b3 = (const float*)d_in[7];
    float* out      = (float*)d_out;
    int E = in_sizes[1] / 2;  // element count is 2E for both int32 and int64

    // --- dtype detect + CSR build ---
    k_detect<<<1, 32>>>(ei32);
    k_zero_cnt<<<(NN + 255) / 256, 256>>>();
    k_count<<<(E + 255) / 256, 256>>>(ei32, E);
    k_dinv<<<(NN + 255) / 256, 256>>>();
    k_scan1<<<SCAN_NBLK, 256>>>();
    k_scan2<<<1, 128>>>();
    k_scan3<<<SCAN_NBLK, 256>>>();
    k_cursor<<<(NN + 255) / 256, 256>>>();
    k_scatter<<<(E + 255) / 256, 256>>>(ei32, E);

    // --- layers (aggregate on the narrow side of each GEMM) ---
    int aggBlocks = (NN * 32 + 255) / 256;
    int gemmBlocks = (NN + 31) / 32;  // 3125

    // layer 1: agg(x)[12] -> GEMM 12->64 (+b1, relu)   x -> buf1 -> buf2
    k_agg<12, false, false><<<aggBlocks, 256>>>(x, 0, nullptr, 1, nullptr);
    k_gemm<12, 64, 12, true, true><<<gemmBlocks, dim3(16, 8)>>>(nullptr, 1, W1, b1, nullptr, 2);

    // layer 2: agg(h1)[64] -> GEMM 64->128 (+b2, relu)   buf2 -> buf1 -> buf2
    k_agg<64, false, false><<<aggBlocks, 256>>>(nullptr, 2, nullptr, 1, nullptr);
    k_gemm<64, 128, 64, true, true><<<gemmBlocks, dim3(32, 8)>>>(nullptr, 1, W2, b2, nullptr, 2);

    // layer 3: GEMM 128->96 (no bias) -> agg[96] (+b3)   buf2 -> buf1 -> out
    k_gemm<128, 96, 64, false, false><<<gemmBlocks, dim3(24, 8)>>>(nullptr, 2, W3, nullptr, nullptr, 1);
    k_agg<96, true, false><<<aggBlocks, 256>>>(nullptr, 1, out, 0, b3);
}